// round 14
// baseline (speedup 1.0000x reference)
#include <cuda_runtime.h>
#include <cstdint>

// out[b,s,d] = x[b,s,d] + enc(s,d); B=8,S=4096,D=1024 fp32. 268 MB traffic.
//
// R14: amplify R13's win. R13 (TMA bulk stores, 4KB chunks) gave the best
// kernel time of the session: 35.39us vs 36.0-37.0 for all STG variants —
// coarse contiguous write transactions reduce DRAM R/W turnaround loss.
// This round doubles the chunk: TPB=512, 8 slices x 8KB staged in 64KB
// dynamic SMEM, 8 x 8KB cp.async.bulk stores per block.

#define B_ 8
#define S_ 4096
#define D_ 1024
#define SD4_ ((S_ * D_) / 4)     // 1,048,576 float4 tiles per batch slice
#define TPB 512
#define SLICE_BYTES (TPB * 16)   // 8192 B contiguous per batch slice per block
#define SMEM_BYTES (B_ * SLICE_BYTES)  // 65536

__global__ __launch_bounds__(TPB) void pe_add_kernel(
    const float4* __restrict__ x, float4* __restrict__ out)
{
    extern __shared__ __align__(128) float4 stage[];   // [B_][TPB]

    const int tid   = threadIdx.x;
    const int idx4  = blockIdx.x * TPB + tid;          // [0, SD4_)
    const int d0    = (idx4 & (D_ / 4 - 1)) << 2;
    const float sf  = (float)(idx4 >> 8);              // s = idx4 / 256

    // Front-batch all 8 batch-slice loads (MLP=8).
    float4 v[B_];
#pragma unroll
    for (int b = 0; b < B_; b++)
        v[b] = x[(long long)b * SD4_ + idx4];

    // Encoding computed once, hidden under in-flight loads.
    const float c = -(13.287712379549449f / 1024.0f); // -log2(1e4)/D
    const float e0 = sinf(sf * exp2f((float)(d0 + 0) * c));
    const float e1 = cosf(sf * exp2f((float)(d0 + 1) * c));
    const float e2 = sinf(sf * exp2f((float)(d0 + 2) * c));
    const float e3 = cosf(sf * exp2f((float)(d0 + 3) * c));

#pragma unroll
    for (int b = 0; b < B_; b++) {
        float4 r = v[b];
        r.x += e0; r.y += e1; r.z += e2; r.w += e3;
        stage[b * TPB + tid] = r;
    }

    __syncthreads();
    // Order generic SMEM writes before async-proxy (TMA) reads of SMEM.
    asm volatile("fence.proxy.async.shared::cta;" ::: "memory");

    // One elected thread issues 8 x 8KB bulk stores (1D, no tensor map).
    if (tid == 0) {
        const long long blk_off = (long long)blockIdx.x * TPB;
#pragma unroll
        for (int b = 0; b < B_; b++) {
            unsigned int saddr;
            asm("{ .reg .u64 t; cvta.to.shared.u64 t, %1; cvt.u32.u64 %0, t; }"
                : "=r"(saddr) : "l"(&stage[b * TPB]));
            float4* gdst = out + (long long)b * SD4_ + blk_off;
            asm volatile(
                "cp.async.bulk.global.shared::cta.bulk_group [%0], [%1], %2;"
                :: "l"(gdst), "r"(saddr), "r"((unsigned int)SLICE_BYTES)
                : "memory");
        }
        asm volatile("cp.async.bulk.commit_group;" ::: "memory");
        // Block may not exit while TMA still reads its SMEM.
        asm volatile("cp.async.bulk.wait_group.read 0;" ::: "memory");
    }
}

extern "C" void kernel_launch(void* const* d_in, const int* in_sizes, int n_in,
                              void* d_out, int out_size)
{
    const float4* x = (const float4*)d_in[0];
    float4* out = (float4*)d_out;
    // 64 KB dynamic SMEM > 48 KB default: opt in (host attribute set,
    // allocation-free, idempotent, capture-safe).
    cudaFuncSetAttribute(pe_add_kernel,
                         cudaFuncAttributeMaxDynamicSharedMemorySize,
                         SMEM_BYTES);
    pe_add_kernel<<<SD4_ / TPB, TPB, SMEM_BYTES>>>(x, out);
}